// round 16
// baseline (speedup 1.0000x reference)
#include <cuda_runtime.h>

// Problem constants
#define HW     900
#define IMG_H  30
#define IMG_W  30
#define NBATCH 2
#define NHEAD  8
#define WS2    225
#define INVT   0.17677669529663687f   // 1/sqrt(32)

#define TROW   32                      // padded tile row stride
#define TPIX   (15 * TROW)             // 480 smem pixels per channel-quad

// ---------------- scratch (device globals: no allocation allowed) ----------
__device__ float g_qkf   [NBATCH * 256 * HW];            // [n][c][p]
__device__ float g_vvp   [NBATCH * 256 * HW];            // [n][c][p]
__device__ float g_uup   [NBATCH * HW * 256];            // [n][p][c]
__device__ float g_gated [NBATCH * HW * 256];            // [n][p][c]
__device__ float g_dwp   [NBATCH * HW * 256];            // [n][p][c]
__device__ float g_attn_fb[NBATCH * NHEAD * WS2 * HW];

// ---------------- fused pre-GEMMs: qkf, v, u in one launch ------------------
// grid (15 p-tiles of 64, 48 tiles of 32 outputs), block 256, thread = 2o x 4p.
__global__ void __launch_bounds__(256, 4) k_pre(
                      const float* __restrict__ q, const float* __restrict__ v,
                      const float* __restrict__ u,
                      const float* __restrict__ Wqk, const float* __restrict__ bqk,
                      const float* __restrict__ Wv,  const float* __restrict__ bv,
                      const float* __restrict__ Wu,  const float* __restrict__ bu) {
    __shared__ float Ws[32 * 34];      // [c][o], stride 34
    __shared__ float Xs[32 * 64];      // [c][p]
    __shared__ float Su[64 * 33];      // [p][o] staging for uup
    int p0 = blockIdx.x * 64;
    int yb = blockIdx.y;
    int tid = threadIdx.x;

    const float *src, *W, *bias;
    int KTOT, o0, n, g = 0, mode;     // mode: 0=qkf, 1=v, 2=u
    if (yb < 16) {
        n = yb >> 3; o0 = (yb & 7) * 32;
        src = q + n * 256 * HW; W = Wqk; bias = bqk; KTOT = 256; mode = 0;
    } else {
        int idx = yb - 16;
        o0 = (idx & 3) * 32;
        g = (idx >> 2) & 1;
        int which = (idx >> 3) & 1;
        n = (idx >> 4) & 1;
        src  = (which ? u  : v ) + (n * 256 + g * 128) * HW;
        W    = (which ? Wu : Wv) + g * 128 * 128;
        bias = (which ? bu : bv) + g * 128;
        KTOT = 128; mode = which ? 2 : 1;
    }

    float acc[2][4];
#pragma unroll
    for (int i = 0; i < 2; i++)
#pragma unroll
        for (int j = 0; j < 4; j++) acc[i][j] = 0.f;
    int tx = tid & 15, ty = tid >> 4;   // tx: p-quad, ty: o-pair

    int wo  = tid >> 3, wc4 = (tid & 7) * 4;   // W: 1 float4 (o, c-quad)
    int xc  = tid >> 4, xp4 = (tid & 15) * 4;  // X: 2 float4 (c and c+16, p-quad)
    bool xok = (p0 + xp4 + 3) < HW;            // only p0=896 tile has invalid quads
    const float* Wg = W + (o0 + wo) * KTOT + wc4;
    const float* Xg = src + xc * HW + p0 + xp4;
    float* WsP = Ws + wc4 * 34 + wo;
    float* XsP = Xs + xc * 64 + xp4;

    float4 wr, xr0, xr1;
    wr  = *reinterpret_cast<const float4*>(Wg);
    xr0 = xok ? *reinterpret_cast<const float4*>(Xg)
              : make_float4(0.f, 0.f, 0.f, 0.f);
    xr1 = xok ? *reinterpret_cast<const float4*>(Xg + 16 * HW)
              : make_float4(0.f, 0.f, 0.f, 0.f);

    for (int c0 = 0; c0 < KTOT; c0 += 32) {
        WsP[0 * 34] = wr.x;
        WsP[1 * 34] = wr.y;
        WsP[2 * 34] = wr.z;
        WsP[3 * 34] = wr.w;
        *reinterpret_cast<float4*>(XsP)            = xr0;
        *reinterpret_cast<float4*>(XsP + 16 * 64)  = xr1;
        __syncthreads();
        if (c0 + 32 < KTOT) {
            Wg += 32;
            Xg += 32 * HW;
            wr  = *reinterpret_cast<const float4*>(Wg);
            xr0 = xok ? *reinterpret_cast<const float4*>(Xg)
                      : make_float4(0.f, 0.f, 0.f, 0.f);
            xr1 = xok ? *reinterpret_cast<const float4*>(Xg + 16 * HW)
                      : make_float4(0.f, 0.f, 0.f, 0.f);
        }
#pragma unroll
        for (int c = 0; c < 32; c++) {
            float2 a2 = *reinterpret_cast<const float2*>(&Ws[c * 34 + ty * 2]);
            float4 b4 = *reinterpret_cast<const float4*>(&Xs[c * 64 + tx * 4]);
            acc[0][0] += a2.x * b4.x; acc[0][1] += a2.x * b4.y;
            acc[0][2] += a2.x * b4.z; acc[0][3] += a2.x * b4.w;
            acc[1][0] += a2.y * b4.x; acc[1][1] += a2.y * b4.y;
            acc[1][2] += a2.y * b4.z; acc[1][3] += a2.y * b4.w;
        }
        __syncthreads();
    }

    if (mode == 0) {
#pragma unroll
        for (int i = 0; i < 2; i++) {
            int o = o0 + ty * 2 + i;
            float bb = bias[o];
#pragma unroll
            for (int j = 0; j < 4; j++) {
                int p = p0 + tx * 4 + j;
                if (p < HW) g_qkf[(n * 256 + o) * HW + p] = acc[i][j] + bb;
            }
        }
    } else if (mode == 1) {
#pragma unroll
        for (int i = 0; i < 2; i++) {
            int o = o0 + ty * 2 + i;
            float bb = bias[o];
            int d = (o >> 4) * 32 + g * 16 + (o & 15);
#pragma unroll
            for (int j = 0; j < 4; j++) {
                int p = p0 + tx * 4 + j;
                if (p < HW) {
                    float val = acc[i][j] + bb;
                    val = val / (1.f + __expf(-val));
                    g_vvp[(n * 256 + d) * HW + p] = val;
                }
            }
        }
    } else {
#pragma unroll
        for (int i = 0; i < 2; i++) {
            int o = o0 + ty * 2 + i;
            float bb = bias[o];
#pragma unroll
            for (int j = 0; j < 4; j++) {
                float val = acc[i][j] + bb;
                Su[(tx * 4 + j) * 33 + ty * 2 + i] = val / (1.f + __expf(-val));
            }
        }
        __syncthreads();
        for (int idx = tid; idx < 2048; idx += 256) {
            int pl = idx >> 5, ol = idx & 31;
            int p = p0 + pl;
            if (p < HW) {
                int o = o0 + ol;
                int d = (o >> 4) * 32 + g * 16 + (o & 15);
                g_uup[(n * HW + p) * 256 + d] = Su[pl * 33 + ol];
            }
        }
    }
}

// ---------------- fused windowed attention ---------------------------------
// grid (30 rows, 8 heads, 2 batch), block 960 (warp = pixel).
__global__ void __launch_bounds__(960, 1) k_attn(float* __restrict__ attn_out,
                                                 const float* __restrict__ Wrel,
                                                 const float* __restrict__ brel) {
    extern __shared__ float sm[];
    float4* k4    = reinterpret_cast<float4*>(sm);           // [8][TPIX]
    float4* v4    = k4 + 8 * TPIX;                           // [8][TPIX]
    float4* Wrs   = v4 + 8 * TPIX;                           // [8][225]
    float*  brs   = sm + (2 * 8 * TPIX + 8 * WS2) * 4;       // [225]
    float*  a_buf = brs + WS2;                               // [225][30]
    int y0 = blockIdx.x, head = blockIdx.y, n = blockIdx.z;
    int nh = n * NHEAD + head;
    const float* qf = g_qkf + (n * 256 + head * 32) * HW;
    const float* vv = g_vvp + (n * 256 + head * 32) * HW;
    int tid = threadIdx.x;

    for (int i = tid; i < 8 * WS2; i += 960) {
        int o = i >> 3, c4 = i & 7;
        float4 w = *reinterpret_cast<const float4*>(&Wrel[(head * WS2 + o) * 32 + c4 * 4]);
        Wrs[c4 * WS2 + o] = w;
    }
    for (int i = tid; i < WS2; i += 960) brs[i] = brel[head * WS2 + i];

    for (int i = tid; i < 8 * TPIX; i += 960) {
        int c4 = i / TPIX, idx = i - c4 * TPIX;
        int ty = idx >> 5, nx = idx & 31;
        int gy = y0 - 7 + ty;
        float4 kk = {0.f, 0.f, 0.f, 0.f}, vk = {0.f, 0.f, 0.f, 0.f};
        if (gy >= 0 && gy < IMG_H && nx < IMG_W) {
            int gp = gy * IMG_W + nx;
            int cb = c4 * 4;
            kk.x = qf[(cb + 0) * HW + gp]; kk.y = qf[(cb + 1) * HW + gp];
            kk.z = qf[(cb + 2) * HW + gp]; kk.w = qf[(cb + 3) * HW + gp];
            vk.x = vv[(cb + 0) * HW + gp]; vk.y = vv[(cb + 1) * HW + gp];
            vk.z = vv[(cb + 2) * HW + gp]; vk.w = vv[(cb + 3) * HW + gp];
        }
        k4[i] = kk;
        v4[i] = vk;
    }
    __syncthreads();

    int w    = tid >> 5;   // warp index (0..29)
    int lane = tid & 31;
    int x = w;
    int p = y0 * IMG_W + x;
    int qidx = 7 * TROW + x;

    // ---- rel phase: warp w computes o = w + 30j for all pixels (lane = px)
    {
        int px = lane;                 // 30,31 read pad, don't store
        float4 qreg[8];
#pragma unroll
        for (int c4 = 0; c4 < 8; c4++) qreg[c4] = k4[c4 * TPIX + 7 * TROW + px];
#pragma unroll
        for (int j = 0; j < 8; j++) {
            int o = w + 30 * j;
            if (o < WS2) {
                float acc = 0.f;
#pragma unroll
                for (int c4 = 0; c4 < 8; c4++) {
                    float4 wr = Wrs[c4 * WS2 + o];   // broadcast across lanes
                    acc += qreg[c4].x * wr.x + qreg[c4].y * wr.y
                         + qreg[c4].z * wr.z + qreg[c4].w * wr.w;
                }
                if (px < 30) a_buf[o * 30 + px] = acc + brs[o];
            }
        }
    }
    __syncthreads();

    // ---- score phase
    unsigned vmask = 0;
    float av[8];
#pragma unroll
    for (int i = 0; i < 8; i++) av[i] = 0.f;
#pragma unroll
    for (int i = 0; i < 8; i++) {
        int o = i * 32 + lane;
        if (o < WS2) {
            int oy = o / 15, ox = o - oy * 15;
            int ny = y0 + oy - 7, nx = x + ox - 7;
            if (ny >= 0 && ny < IMG_H && nx >= 0 && nx < IMG_W)
                vmask |= 1u << i;
        }
    }
#pragma unroll
    for (int c4 = 0; c4 < 8; c4++) {
        float4 qq = k4[c4 * TPIX + qidx];   // broadcast
#pragma unroll
        for (int i = 0; i < 8; i++) {
            if (vmask & (1u << i)) {
                int o = i * 32 + lane;
                int oy = o / 15;
                int idx = oy * TROW + (x + (o - oy * 15) - 7);
                float4 kk = k4[c4 * TPIX + idx];
                av[i] += qq.x * kk.x + qq.y * kk.y + qq.z * kk.z + qq.w * kk.w;
            }
        }
    }
    float m = -1e30f;
#pragma unroll
    for (int i = 0; i < 8; i++) {
        int o = i * 32 + lane;
        float s = -1e30f;
        if (o < WS2)
            s = (vmask & (1u << i)) ? av[i] * INVT + a_buf[o * 30 + x] : -1e8f;
        av[i] = s;
        m = fmaxf(m, s);
    }
#pragma unroll
    for (int sh = 16; sh; sh >>= 1) m = fmaxf(m, __shfl_xor_sync(0xffffffffu, m, sh));
    float l = 0.f;
#pragma unroll
    for (int i = 0; i < 8; i++) { av[i] = __expf(av[i] - m); l += av[i]; }
#pragma unroll
    for (int sh = 16; sh; sh >>= 1) l += __shfl_xor_sync(0xffffffffu, l, sh);
    float inv_l = 1.f / l;
#pragma unroll
    for (int i = 0; i < 8; i++) {
        av[i] *= inv_l;
        int o = i * 32 + lane;
        if (o < WS2) a_buf[o * 30 + x] = av[i];   // own column: no race
    }

    // ---- aggregation
    float agg[32];
#pragma unroll
    for (int c = 0; c < 32; c++) agg[c] = 0.f;
#pragma unroll
    for (int i = 0; i < 8; i++) {
        if (vmask & (1u << i)) {
            int o = i * 32 + lane;
            int oy = o / 15;
            int idx = oy * TROW + (x + (o - oy * 15) - 7);
            float a = av[i];
#pragma unroll
            for (int c4 = 0; c4 < 8; c4++) {
                float4 vk = v4[c4 * TPIX + idx];
                agg[4 * c4 + 0] += a * vk.x;
                agg[4 * c4 + 1] += a * vk.y;
                agg[4 * c4 + 2] += a * vk.z;
                agg[4 * c4 + 3] += a * vk.w;
            }
        }
    }
#pragma unroll
    for (int sh = 16; sh >= 1; sh >>= 1) {
        bool up = (lane & sh) != 0;
#pragma unroll
        for (int j = 0; j < sh; j++) {
            float send = up ? agg[j] : agg[j + sh];
            float got  = __shfl_xor_sync(0xffffffffu, send, sh);
            agg[j] = (up ? agg[j + sh] : agg[j]) + got;
        }
    }
    float gv = agg[0] * g_uup[(n * HW + p) * 256 + head * 32 + lane];
    g_gated[(n * HW + p) * 256 + head * 32 + lane] = gv;

    __syncthreads();
    float* dst = attn_out + (size_t)nh * WS2 * HW + y0 * IMG_W;
    for (int i = tid; i < WS2 * IMG_W; i += 960) {
        int o = i / 30, px = i - o * 30;
        dst[(size_t)o * HW + px] = a_buf[i];
    }
}

// ---------------- depthwise 5x5 conv + zero-init of proj output ------------
__global__ void k_dw(const float* __restrict__ Wdw, float* __restrict__ out) {
    __shared__ float ws[25 * 256];     // [k][c]
    int tid = threadIdx.x;
    // zero the projection output region (out[0 .. 230400)) for split-K atomics
    {
        int zi = blockIdx.x * 256 + tid;           // 115200 threads, 2 floats each
        *reinterpret_cast<float2*>(out + 2 * zi) = make_float2(0.f, 0.f);
    }
    for (int i = tid; i < 25 * 256; i += 256) {
        int c = i / 25, k = i - c * 25;
        ws[k * 256 + c] = Wdw[i];
    }
    __syncthreads();
    int i = blockIdx.x * 256 + tid;
    int c4 = i & 63;
    int rest = i >> 6;
    int p = rest % HW;
    int n = rest / HW;
    int y = p / IMG_W, x = p - y * IMG_W;
    const float* src = g_gated + (size_t)n * HW * 256;
    float4 acc = {0.f, 0.f, 0.f, 0.f};
#pragma unroll
    for (int ky = 0; ky < 5; ky++) {
        int ny = y + ky - 2;
        if (ny < 0 || ny >= IMG_H) continue;
#pragma unroll
        for (int kx = 0; kx < 5; kx++) {
            int nx = x + kx - 2;
            if (nx < 0 || nx >= IMG_W) continue;
            int k = ky * 5 + kx;
            float4 gk = *reinterpret_cast<const float4*>(&src[(ny * IMG_W + nx) * 256 + c4 * 4]);
            float4 wv = *reinterpret_cast<const float4*>(&ws[k * 256 + c4 * 4]);
            acc.x += wv.x * gk.x; acc.y += wv.y * gk.y;
            acc.z += wv.z * gk.z; acc.w += wv.w * gk.w;
        }
    }
    *reinterpret_cast<float4*>(&g_dwp[((size_t)n * HW + p) * 256 + c4 * 4]) = acc;
}

// ---------------- final projection, split-K x4 via atomicAdd ---------------
// grid (15 p-tiles of 64, 4 o-tiles of 32, 8 = n*4+ks), 256 threads.
// Each block sums K in [ks*64, ks*64+64); ks=0 adds bias. out pre-zeroed.
__global__ void k_proj(const float* __restrict__ Wproj, const float* __restrict__ bproj,
                       float* __restrict__ out) {
    __shared__ float Ws[2][32 * 34];   // [c][o], stride 34
    __shared__ float Xs[2][32 * 68];   // [c][p], stride 68
    int z = blockIdx.z;
    int n = z >> 2, ks = z & 3;
    int o0 = blockIdx.y * 32, p0 = blockIdx.x * 64;
    int cb = ks * 64;
    const float* X = g_dwp + (size_t)n * HW * 256 + cb;
    const float* Wp = Wproj + cb;
    int tid = threadIdx.x;
    int tx = tid & 15, ty = tid >> 4;
    float acc[2][4];
#pragma unroll
    for (int i = 0; i < 2; i++)
#pragma unroll
        for (int j = 0; j < 4; j++) acc[i][j] = 0.f;

    int wo = tid >> 3, wc = (tid & 7) * 4;
    float4 wr, xr0, xr1;
    {
        wr = *reinterpret_cast<const float4*>(&Wp[(o0 + wo) * 256 + wc]);
        int c40 = tid & 7,  pA = tid >> 3;
        int pB = pA + 32;
        int ppA = p0 + pA, ppB = p0 + pB;
        xr0 = (ppA < HW) ? *reinterpret_cast<const float4*>(&X[ppA * 256 + c40 * 4])
                         : make_float4(0.f, 0.f, 0.f, 0.f);
        xr1 = (ppB < HW) ? *reinterpret_cast<const float4*>(&X[ppB * 256 + c40 * 4])
                         : make_float4(0.f, 0.f, 0.f, 0.f);
    }
    int buf = 0;
    for (int c0 = 0; c0 < 64; c0 += 32) {
        Ws[buf][(wc + 0) * 34 + wo] = wr.x;
        Ws[buf][(wc + 1) * 34 + wo] = wr.y;
        Ws[buf][(wc + 2) * 34 + wo] = wr.z;
        Ws[buf][(wc + 3) * 34 + wo] = wr.w;
        {
            int c40 = tid & 7, pA = tid >> 3, pB = pA + 32;
            Xs[buf][(c40 * 4 + 0) * 68 + pA] = xr0.x;
            Xs[buf][(c40 * 4 + 1) * 68 + pA] = xr0.y;
            Xs[buf][(c40 * 4 + 2) * 68 + pA] = xr0.z;
            Xs[buf][(c40 * 4 + 3) * 68 + pA] = xr0.w;
            Xs[buf][(c40 * 4 + 0) * 68 + pB] = xr1.x;
            Xs[buf][(c40 * 4 + 1) * 68 + pB] = xr1.y;
            Xs[buf][(c40 * 4 + 2) * 68 + pB] = xr1.z;
            Xs[buf][(c40 * 4 + 3) * 68 + pB] = xr1.w;
        }
        __syncthreads();
        if (c0 + 32 < 64) {
            int c1 = c0 + 32;
            wr = *reinterpret_cast<const float4*>(&Wp[(o0 + wo) * 256 + c1 + wc]);
            int c40 = tid & 7, pA = tid >> 3, pB = pA + 32;
            int ppA = p0 + pA, ppB = p0 + pB;
            xr0 = (ppA < HW) ? *reinterpret_cast<const float4*>(&X[ppA * 256 + c1 + c40 * 4])
                             : make_float4(0.f, 0.f, 0.f, 0.f);
            xr1 = (ppB < HW) ? *reinterpret_cast<const float4*>(&X[ppB * 256 + c1 + c40 * 4])
                             : make_float4(0.f, 0.f, 0.f, 0.f);
        }
#pragma unroll
        for (int c = 0; c < 32; c++) {
            float a0 = Ws[buf][c * 34 + ty * 2 + 0];
            float a1 = Ws[buf][c * 34 + ty * 2 + 1];
            float4 b4 = *reinterpret_cast<const float4*>(&Xs[buf][c * 68 + tx * 4]);
            acc[0][0] += a0 * b4.x; acc[0][1] += a0 * b4.y;
            acc[0][2] += a0 * b4.z; acc[0][3] += a0 * b4.w;
            acc[1][0] += a1 * b4.x; acc[1][1] += a1 * b4.y;
            acc[1][2] += a1 * b4.z; acc[1][3] += a1 * b4.w;
        }
        buf ^= 1;
    }
    __syncthreads();
#pragma unroll
    for (int i = 0; i < 2; i++) {
        int o = o0 + ty * 2 + i;
        float bb = (ks == 0) ? bproj[o] : 0.f;
#pragma unroll
        for (int j = 0; j < 4; j++) {
            int p = p0 + tx * 4 + j;
            if (p < HW)
                atomicAdd(&out[p * (NBATCH * 128) + n * 128 + o], acc[i][j] + bb);
        }
    }
}

// ---------------------------------------------------------------------------
extern "C" void kernel_launch(void* const* d_in, const int* in_sizes, int n_in,
                              void* d_out, int out_size) {
    const float* q     = (const float*)d_in[0];
    const float* v     = (const float*)d_in[2];
    const float* u     = (const float*)d_in[3];
    const float* Wqk   = (const float*)d_in[4];
    const float* bqk   = (const float*)d_in[5];
    const float* Wv    = (const float*)d_in[6];
    const float* bv    = (const float*)d_in[7];
    const float* Wu    = (const float*)d_in[8];
    const float* bu    = (const float*)d_in[9];
    const float* Wrel  = (const float*)d_in[10];
    const float* brel  = (const float*)d_in[11];
    const float* Wdw   = (const float*)d_in[12];
    const float* Wproj = (const float*)d_in[13];
    const float* bproj = (const float*)d_in[14];
    float* out = (float*)d_out;

    const int OUT0 = HW * NBATCH * 128;                 // 230400
    const int OUT1 = NBATCH * NHEAD * WS2 * HW;         // 3240000
    int use_ext = (out_size >= OUT0 + OUT1) ? 1 : 0;

    float* attn_dst;
    if (use_ext) attn_dst = out + OUT0;
    else         cudaGetSymbolAddress((void**)&attn_dst, g_attn_fb);

    const int attn_smem = (2 * 32 * TPIX + 32 * WS2 + WS2 + 30 * WS2) * (int)sizeof(float);
    cudaFuncSetAttribute(k_attn, cudaFuncAttributeMaxDynamicSharedMemorySize, attn_smem);

    k_pre <<<dim3(15, 48),   256>>>(q, v, u, Wqk, bqk, Wv, bv, Wu, bu);
    k_attn<<<dim3(30, 8, 2), 960, attn_smem>>>(attn_dst, Wrel, brel);
    k_dw  <<<dim3(450),      256>>>(Wdw, out);
    k_proj<<<dim3(15, 4, 8), 256>>>(Wproj, bproj, out);
}

// round 17
// speedup vs baseline: 1.0028x; 1.0028x over previous
#include <cuda_runtime.h>

// Problem constants
#define HW     900
#define IMG_H  30
#define IMG_W  30
#define NBATCH 2
#define NHEAD  8
#define WS2    225
#define INVT   0.17677669529663687f   // 1/sqrt(32)

#define TROW   32                      // padded tile row stride
#define TPIX   (15 * TROW)             // 480 smem pixels per channel-quad
#define ABS    31                      // a_buf row stride (31: conflict-free for o=i*32+lane)

// ---------------- scratch (device globals: no allocation allowed) ----------
__device__ float g_qkf   [NBATCH * 256 * HW];            // [n][c][p]
__device__ float g_vvp   [NBATCH * 256 * HW];            // [n][c][p]
__device__ float g_uup   [NBATCH * HW * 256];            // [n][p][c]
__device__ float g_gated [NBATCH * HW * 256];            // [n][p][c]
__device__ float g_dwp   [NBATCH * HW * 256];            // [n][p][c]
__device__ float g_attn_fb[NBATCH * NHEAD * WS2 * HW];

// ---------------- fused pre-GEMMs: qkf, v, u in one launch ------------------
// grid (15 p-tiles of 64, 48 tiles of 32 outputs), block 256, thread = 2o x 4p.
__global__ void __launch_bounds__(256, 4) k_pre(
                      const float* __restrict__ q, const float* __restrict__ v,
                      const float* __restrict__ u,
                      const float* __restrict__ Wqk, const float* __restrict__ bqk,
                      const float* __restrict__ Wv,  const float* __restrict__ bv,
                      const float* __restrict__ Wu,  const float* __restrict__ bu) {
    __shared__ float Ws[32 * 34];      // [c][o], stride 34
    __shared__ float Xs[32 * 64];      // [c][p]
    __shared__ float Su[64 * 33];      // [p][o] staging for uup
    int p0 = blockIdx.x * 64;
    int yb = blockIdx.y;
    int tid = threadIdx.x;

    const float *src, *W, *bias;
    int KTOT, o0, n, g = 0, mode;     // mode: 0=qkf, 1=v, 2=u
    if (yb < 16) {
        n = yb >> 3; o0 = (yb & 7) * 32;
        src = q + n * 256 * HW; W = Wqk; bias = bqk; KTOT = 256; mode = 0;
    } else {
        int idx = yb - 16;
        o0 = (idx & 3) * 32;
        g = (idx >> 2) & 1;
        int which = (idx >> 3) & 1;
        n = (idx >> 4) & 1;
        src  = (which ? u  : v ) + (n * 256 + g * 128) * HW;
        W    = (which ? Wu : Wv) + g * 128 * 128;
        bias = (which ? bu : bv) + g * 128;
        KTOT = 128; mode = which ? 2 : 1;
    }

    float acc[2][4];
#pragma unroll
    for (int i = 0; i < 2; i++)
#pragma unroll
        for (int j = 0; j < 4; j++) acc[i][j] = 0.f;
    int tx = tid & 15, ty = tid >> 4;   // tx: p-quad, ty: o-pair

    int wo  = tid >> 3, wc4 = (tid & 7) * 4;   // W: 1 float4 (o, c-quad)
    int xc  = tid >> 4, xp4 = (tid & 15) * 4;  // X: 2 float4 (c and c+16, p-quad)
    bool xok = (p0 + xp4 + 3) < HW;            // only p0=896 tile has invalid quads
    const float* Wg = W + (o0 + wo) * KTOT + wc4;
    const float* Xg = src + xc * HW + p0 + xp4;
    float* WsP = Ws + wc4 * 34 + wo;
    float* XsP = Xs + xc * 64 + xp4;

    float4 wr, xr0, xr1;
    wr  = *reinterpret_cast<const float4*>(Wg);
    xr0 = xok ? *reinterpret_cast<const float4*>(Xg)
              : make_float4(0.f, 0.f, 0.f, 0.f);
    xr1 = xok ? *reinterpret_cast<const float4*>(Xg + 16 * HW)
              : make_float4(0.f, 0.f, 0.f, 0.f);

    for (int c0 = 0; c0 < KTOT; c0 += 32) {
        WsP[0 * 34] = wr.x;
        WsP[1 * 34] = wr.y;
        WsP[2 * 34] = wr.z;
        WsP[3 * 34] = wr.w;
        *reinterpret_cast<float4*>(XsP)            = xr0;
        *reinterpret_cast<float4*>(XsP + 16 * 64)  = xr1;
        __syncthreads();
        if (c0 + 32 < KTOT) {
            Wg += 32;
            Xg += 32 * HW;
            wr  = *reinterpret_cast<const float4*>(Wg);
            xr0 = xok ? *reinterpret_cast<const float4*>(Xg)
                      : make_float4(0.f, 0.f, 0.f, 0.f);
            xr1 = xok ? *reinterpret_cast<const float4*>(Xg + 16 * HW)
                      : make_float4(0.f, 0.f, 0.f, 0.f);
        }
#pragma unroll
        for (int c = 0; c < 32; c++) {
            float2 a2 = *reinterpret_cast<const float2*>(&Ws[c * 34 + ty * 2]);
            float4 b4 = *reinterpret_cast<const float4*>(&Xs[c * 64 + tx * 4]);
            acc[0][0] += a2.x * b4.x; acc[0][1] += a2.x * b4.y;
            acc[0][2] += a2.x * b4.z; acc[0][3] += a2.x * b4.w;
            acc[1][0] += a2.y * b4.x; acc[1][1] += a2.y * b4.y;
            acc[1][2] += a2.y * b4.z; acc[1][3] += a2.y * b4.w;
        }
        __syncthreads();
    }

    if (mode == 0) {
#pragma unroll
        for (int i = 0; i < 2; i++) {
            int o = o0 + ty * 2 + i;
            float bb = bias[o];
#pragma unroll
            for (int j = 0; j < 4; j++) {
                int p = p0 + tx * 4 + j;
                if (p < HW) g_qkf[(n * 256 + o) * HW + p] = acc[i][j] + bb;
            }
        }
    } else if (mode == 1) {
#pragma unroll
        for (int i = 0; i < 2; i++) {
            int o = o0 + ty * 2 + i;
            float bb = bias[o];
            int d = (o >> 4) * 32 + g * 16 + (o & 15);
#pragma unroll
            for (int j = 0; j < 4; j++) {
                int p = p0 + tx * 4 + j;
                if (p < HW) {
                    float val = acc[i][j] + bb;
                    val = val / (1.f + __expf(-val));
                    g_vvp[(n * 256 + d) * HW + p] = val;
                }
            }
        }
    } else {
#pragma unroll
        for (int i = 0; i < 2; i++) {
            int o = o0 + ty * 2 + i;
            float bb = bias[o];
#pragma unroll
            for (int j = 0; j < 4; j++) {
                float val = acc[i][j] + bb;
                Su[(tx * 4 + j) * 33 + ty * 2 + i] = val / (1.f + __expf(-val));
            }
        }
        __syncthreads();
        for (int idx = tid; idx < 2048; idx += 256) {
            int pl = idx >> 5, ol = idx & 31;
            int p = p0 + pl;
            if (p < HW) {
                int o = o0 + ol;
                int d = (o >> 4) * 32 + g * 16 + (o & 15);
                g_uup[(n * HW + p) * 256 + d] = Su[pl * 33 + ol];
            }
        }
    }
}

// ---------------- fused windowed attention ---------------------------------
// grid (30 rows, 8 heads, 2 batch), block 960 (warp = pixel).
// a_buf stride = 31: lanes o=i*32+lane map to distinct banks (31*32 ≡ -32 mod 32... 
// (i*32+lane)*31 mod 32 = -lane mod 32 -> conflict-free).
__global__ void __launch_bounds__(960, 1) k_attn(float* __restrict__ attn_out,
                                                 const float* __restrict__ Wrel,
                                                 const float* __restrict__ brel) {
    extern __shared__ float sm[];
    float4* k4    = reinterpret_cast<float4*>(sm);           // [8][TPIX]
    float4* v4    = k4 + 8 * TPIX;                           // [8][TPIX]
    float4* Wrs   = v4 + 8 * TPIX;                           // [8][225]
    float*  brs   = sm + (2 * 8 * TPIX + 8 * WS2) * 4;       // [225]
    float*  a_buf = brs + WS2;                               // [225][ABS]
    int y0 = blockIdx.x, head = blockIdx.y, n = blockIdx.z;
    int nh = n * NHEAD + head;
    const float* qf = g_qkf + (n * 256 + head * 32) * HW;
    const float* vv = g_vvp + (n * 256 + head * 32) * HW;
    int tid = threadIdx.x;

    for (int i = tid; i < 8 * WS2; i += 960) {
        int o = i >> 3, c4 = i & 7;
        float4 w = *reinterpret_cast<const float4*>(&Wrel[(head * WS2 + o) * 32 + c4 * 4]);
        Wrs[c4 * WS2 + o] = w;
    }
    for (int i = tid; i < WS2; i += 960) brs[i] = brel[head * WS2 + i];

    for (int i = tid; i < 8 * TPIX; i += 960) {
        int c4 = i / TPIX, idx = i - c4 * TPIX;
        int ty = idx >> 5, nx = idx & 31;
        int gy = y0 - 7 + ty;
        float4 kk = {0.f, 0.f, 0.f, 0.f}, vk = {0.f, 0.f, 0.f, 0.f};
        if (gy >= 0 && gy < IMG_H && nx < IMG_W) {
            int gp = gy * IMG_W + nx;
            int cb = c4 * 4;
            kk.x = qf[(cb + 0) * HW + gp]; kk.y = qf[(cb + 1) * HW + gp];
            kk.z = qf[(cb + 2) * HW + gp]; kk.w = qf[(cb + 3) * HW + gp];
            vk.x = vv[(cb + 0) * HW + gp]; vk.y = vv[(cb + 1) * HW + gp];
            vk.z = vv[(cb + 2) * HW + gp]; vk.w = vv[(cb + 3) * HW + gp];
        }
        k4[i] = kk;
        v4[i] = vk;
    }
    __syncthreads();

    int w    = tid >> 5;   // warp index (0..29)
    int lane = tid & 31;
    int x = w;
    int p = y0 * IMG_W + x;
    int qidx = 7 * TROW + x;

    // ---- rel phase: warp w computes o = w + 30j for all pixels (lane = px)
    {
        int px = lane;                 // 30,31 read pad, don't store
        float4 qreg[8];
#pragma unroll
        for (int c4 = 0; c4 < 8; c4++) qreg[c4] = k4[c4 * TPIX + 7 * TROW + px];
#pragma unroll
        for (int j = 0; j < 8; j++) {
            int o = w + 30 * j;
            if (o < WS2) {
                float acc = 0.f;
#pragma unroll
                for (int c4 = 0; c4 < 8; c4++) {
                    float4 wr = Wrs[c4 * WS2 + o];   // broadcast across lanes
                    acc += qreg[c4].x * wr.x + qreg[c4].y * wr.y
                         + qreg[c4].z * wr.z + qreg[c4].w * wr.w;
                }
                if (px < 30) a_buf[o * ABS + px] = acc + brs[o];
            }
        }
    }
    __syncthreads();

    // ---- score phase
    unsigned vmask = 0;
    float av[8];
#pragma unroll
    for (int i = 0; i < 8; i++) av[i] = 0.f;
#pragma unroll
    for (int i = 0; i < 8; i++) {
        int o = i * 32 + lane;
        if (o < WS2) {
            int oy = o / 15, ox = o - oy * 15;
            int ny = y0 + oy - 7, nx = x + ox - 7;
            if (ny >= 0 && ny < IMG_H && nx >= 0 && nx < IMG_W)
                vmask |= 1u << i;
        }
    }
#pragma unroll
    for (int c4 = 0; c4 < 8; c4++) {
        float4 qq = k4[c4 * TPIX + qidx];   // broadcast
#pragma unroll
        for (int i = 0; i < 8; i++) {
            if (vmask & (1u << i)) {
                int o = i * 32 + lane;
                int oy = o / 15;
                int idx = oy * TROW + (x + (o - oy * 15) - 7);
                float4 kk = k4[c4 * TPIX + idx];
                av[i] += qq.x * kk.x + qq.y * kk.y + qq.z * kk.z + qq.w * kk.w;
            }
        }
    }
    float m = -1e30f;
#pragma unroll
    for (int i = 0; i < 8; i++) {
        int o = i * 32 + lane;
        float s = -1e30f;
        if (o < WS2)
            s = (vmask & (1u << i)) ? av[i] * INVT + a_buf[o * ABS + x] : -1e8f;
        av[i] = s;
        m = fmaxf(m, s);
    }
#pragma unroll
    for (int sh = 16; sh; sh >>= 1) m = fmaxf(m, __shfl_xor_sync(0xffffffffu, m, sh));
    float l = 0.f;
#pragma unroll
    for (int i = 0; i < 8; i++) { av[i] = __expf(av[i] - m); l += av[i]; }
#pragma unroll
    for (int sh = 16; sh; sh >>= 1) l += __shfl_xor_sync(0xffffffffu, l, sh);
    float inv_l = 1.f / l;
#pragma unroll
    for (int i = 0; i < 8; i++) {
        av[i] *= inv_l;
        int o = i * 32 + lane;
        if (o < WS2) a_buf[o * ABS + x] = av[i];   // own column: no race
    }

    // ---- aggregation
    float agg[32];
#pragma unroll
    for (int c = 0; c < 32; c++) agg[c] = 0.f;
#pragma unroll
    for (int i = 0; i < 8; i++) {
        if (vmask & (1u << i)) {
            int o = i * 32 + lane;
            int oy = o / 15;
            int idx = oy * TROW + (x + (o - oy * 15) - 7);
            float a = av[i];
#pragma unroll
            for (int c4 = 0; c4 < 8; c4++) {
                float4 vk = v4[c4 * TPIX + idx];
                agg[4 * c4 + 0] += a * vk.x;
                agg[4 * c4 + 1] += a * vk.y;
                agg[4 * c4 + 2] += a * vk.z;
                agg[4 * c4 + 3] += a * vk.w;
            }
        }
    }
#pragma unroll
    for (int sh = 16; sh >= 1; sh >>= 1) {
        bool up = (lane & sh) != 0;
#pragma unroll
        for (int j = 0; j < sh; j++) {
            float send = up ? agg[j] : agg[j + sh];
            float got  = __shfl_xor_sync(0xffffffffu, send, sh);
            agg[j] = (up ? agg[j + sh] : agg[j]) + got;
        }
    }
    float gv = agg[0] * g_uup[(n * HW + p) * 256 + head * 32 + lane];
    g_gated[(n * HW + p) * 256 + head * 32 + lane] = gv;

    __syncthreads();
    float* dst = attn_out + (size_t)nh * WS2 * HW + y0 * IMG_W;
    for (int i = tid; i < WS2 * IMG_W; i += 960) {
        int o = i / 30, px = i - o * 30;
        dst[(size_t)o * HW + px] = a_buf[o * ABS + px];
    }
}

// ---------------- depthwise 5x5 conv + zero-init of proj output ------------
__global__ void k_dw(const float* __restrict__ Wdw, float* __restrict__ out) {
    __shared__ float ws[25 * 256];     // [k][c]
    int tid = threadIdx.x;
    {
        int zi = blockIdx.x * 256 + tid;           // 115200 threads, 2 floats each
        *reinterpret_cast<float2*>(out + 2 * zi) = make_float2(0.f, 0.f);
    }
    for (int i = tid; i < 25 * 256; i += 256) {
        int c = i / 25, k = i - c * 25;
        ws[k * 256 + c] = Wdw[i];
    }
    __syncthreads();
    int i = blockIdx.x * 256 + tid;
    int c4 = i & 63;
    int rest = i >> 6;
    int p = rest % HW;
    int n = rest / HW;
    int y = p / IMG_W, x = p - y * IMG_W;
    const float* src = g_gated + (size_t)n * HW * 256;
    float4 acc = {0.f, 0.f, 0.f, 0.f};
#pragma unroll
    for (int ky = 0; ky < 5; ky++) {
        int ny = y + ky - 2;
        if (ny < 0 || ny >= IMG_H) continue;
#pragma unroll
        for (int kx = 0; kx < 5; kx++) {
            int nx = x + kx - 2;
            if (nx < 0 || nx >= IMG_W) continue;
            int k = ky * 5 + kx;
            float4 gk = *reinterpret_cast<const float4*>(&src[(ny * IMG_W + nx) * 256 + c4 * 4]);
            float4 wv = *reinterpret_cast<const float4*>(&ws[k * 256 + c4 * 4]);
            acc.x += wv.x * gk.x; acc.y += wv.y * gk.y;
            acc.z += wv.z * gk.z; acc.w += wv.w * gk.w;
        }
    }
    *reinterpret_cast<float4*>(&g_dwp[((size_t)n * HW + p) * 256 + c4 * 4]) = acc;
}

// ---------------- final projection, split-K x4 via atomicAdd ---------------
__global__ void k_proj(const float* __restrict__ Wproj, const float* __restrict__ bproj,
                       float* __restrict__ out) {
    __shared__ float Ws[2][32 * 34];   // [c][o], stride 34
    __shared__ float Xs[2][32 * 68];   // [c][p], stride 68
    int z = blockIdx.z;
    int n = z >> 2, ks = z & 3;
    int o0 = blockIdx.y * 32, p0 = blockIdx.x * 64;
    int cb = ks * 64;
    const float* X = g_dwp + (size_t)n * HW * 256 + cb;
    const float* Wp = Wproj + cb;
    int tid = threadIdx.x;
    int tx = tid & 15, ty = tid >> 4;
    float acc[2][4];
#pragma unroll
    for (int i = 0; i < 2; i++)
#pragma unroll
        for (int j = 0; j < 4; j++) acc[i][j] = 0.f;

    int wo = tid >> 3, wc = (tid & 7) * 4;
    float4 wr, xr0, xr1;
    {
        wr = *reinterpret_cast<const float4*>(&Wp[(o0 + wo) * 256 + wc]);
        int c40 = tid & 7,  pA = tid >> 3;
        int pB = pA + 32;
        int ppA = p0 + pA, ppB = p0 + pB;
        xr0 = (ppA < HW) ? *reinterpret_cast<const float4*>(&X[ppA * 256 + c40 * 4])
                         : make_float4(0.f, 0.f, 0.f, 0.f);
        xr1 = (ppB < HW) ? *reinterpret_cast<const float4*>(&X[ppB * 256 + c40 * 4])
                         : make_float4(0.f, 0.f, 0.f, 0.f);
    }
    int buf = 0;
    for (int c0 = 0; c0 < 64; c0 += 32) {
        Ws[buf][(wc + 0) * 34 + wo] = wr.x;
        Ws[buf][(wc + 1) * 34 + wo] = wr.y;
        Ws[buf][(wc + 2) * 34 + wo] = wr.z;
        Ws[buf][(wc + 3) * 34 + wo] = wr.w;
        {
            int c40 = tid & 7, pA = tid >> 3, pB = pA + 32;
            Xs[buf][(c40 * 4 + 0) * 68 + pA] = xr0.x;
            Xs[buf][(c40 * 4 + 1) * 68 + pA] = xr0.y;
            Xs[buf][(c40 * 4 + 2) * 68 + pA] = xr0.z;
            Xs[buf][(c40 * 4 + 3) * 68 + pA] = xr0.w;
            Xs[buf][(c40 * 4 + 0) * 68 + pB] = xr1.x;
            Xs[buf][(c40 * 4 + 1) * 68 + pB] = xr1.y;
            Xs[buf][(c40 * 4 + 2) * 68 + pB] = xr1.z;
            Xs[buf][(c40 * 4 + 3) * 68 + pB] = xr1.w;
        }
        __syncthreads();
        if (c0 + 32 < 64) {
            int c1 = c0 + 32;
            wr = *reinterpret_cast<const float4*>(&Wp[(o0 + wo) * 256 + c1 + wc]);
            int c40 = tid & 7, pA = tid >> 3, pB = pA + 32;
            int ppA = p0 + pA, ppB = p0 + pB;
            xr0 = (ppA < HW) ? *reinterpret_cast<const float4*>(&X[ppA * 256 + c1 + c40 * 4])
                             : make_float4(0.f, 0.f, 0.f, 0.f);
            xr1 = (ppB < HW) ? *reinterpret_cast<const float4*>(&X[ppB * 256 + c1 + c40 * 4])
                             : make_float4(0.f, 0.f, 0.f, 0.f);
        }
#pragma unroll
        for (int c = 0; c < 32; c++) {
            float a0 = Ws[buf][c * 34 + ty * 2 + 0];
            float a1 = Ws[buf][c * 34 + ty * 2 + 1];
            float4 b4 = *reinterpret_cast<const float4*>(&Xs[buf][c * 68 + tx * 4]);
            acc[0][0] += a0 * b4.x; acc[0][1] += a0 * b4.y;
            acc[0][2] += a0 * b4.z; acc[0][3] += a0 * b4.w;
            acc[1][0] += a1 * b4.x; acc[1][1] += a1 * b4.y;
            acc[1][2] += a1 * b4.z; acc[1][3] += a1 * b4.w;
        }
        buf ^= 1;
    }
    __syncthreads();
#pragma unroll
    for (int i = 0; i < 2; i++) {
        int o = o0 + ty * 2 + i;
        float bb = (ks == 0) ? bproj[o] : 0.f;
#pragma unroll
        for (int j = 0; j < 4; j++) {
            int p = p0 + tx * 4 + j;
            if (p < HW)
                atomicAdd(&out[p * (NBATCH * 128) + n * 128 + o], acc[i][j] + bb);
        }
    }
}

// ---------------------------------------------------------------------------
extern "C" void kernel_launch(void* const* d_in, const int* in_sizes, int n_in,
                              void* d_out, int out_size) {
    const float* q     = (const float*)d_in[0];
    const float* v     = (const float*)d_in[2];
    const float* u     = (const float*)d_in[3];
    const float* Wqk   = (const float*)d_in[4];
    const float* bqk   = (const float*)d_in[5];
    const float* Wv    = (const float*)d_in[6];
    const float* bv    = (const float*)d_in[7];
    const float* Wu    = (const float*)d_in[8];
    const float* bu    = (const float*)d_in[9];
    const float* Wrel  = (const float*)d_in[10];
    const float* brel  = (const float*)d_in[11];
    const float* Wdw   = (const float*)d_in[12];
    const float* Wproj = (const float*)d_in[13];
    const float* bproj = (const float*)d_in[14];
    float* out = (float*)d_out;

    const int OUT0 = HW * NBATCH * 128;                 // 230400
    const int OUT1 = NBATCH * NHEAD * WS2 * HW;         // 3240000
    int use_ext = (out_size >= OUT0 + OUT1) ? 1 : 0;

    float* attn_dst;
    if (use_ext) attn_dst = out + OUT0;
    else         cudaGetSymbolAddress((void**)&attn_dst, g_attn_fb);

    const int attn_smem = (2 * 32 * TPIX + 32 * WS2 + WS2 + ABS * WS2) * (int)sizeof(float);
    cudaFuncSetAttribute(k_attn, cudaFuncAttributeMaxDynamicSharedMemorySize, attn_smem);

    k_pre <<<dim3(15, 48),   256>>>(q, v, u, Wqk, bqk, Wv, bv, Wu, bu);
    k_attn<<<dim3(30, 8, 2), 960, attn_smem>>>(attn_dst, Wrel, brel);
    k_dw  <<<dim3(450),      256>>>(Wdw, out);
    k_proj<<<dim3(15, 4, 8), 256>>>(Wproj, bproj, out);
}